// round 5
// baseline (speedup 1.0000x reference)
#include <cuda_runtime.h>
#include <cuda_bf16.h>
#include <cstdint>

// ---------------- scratch ----------------------------------------------------
__device__ float g_kt1[32 * 1024];               // FWHT2D(filter1)/32768
__device__ float g_kt2[64 * 256];                // FWHT2D(filter2)/4096
__device__ __nv_bfloat16 g_ahi[2048 * 4096];     // activations hi
__device__ __nv_bfloat16 g_alo[2048 * 4096];     // activations lo
__device__ __nv_bfloat16 g_whi[512 * 4096];      // fc1 weights hi
__device__ __nv_bfloat16 g_wlo[512 * 4096];      // fc1 weights lo
__device__ float g_h[2048 * 512];                // fc1 output (post bias+relu)

// ---------------- PTX helpers (baseline ISA only) -----------------------------
__device__ __forceinline__ uint32_t smem_u32(const void* p) {
    uint32_t a;
    asm("{ .reg .u64 t; cvta.to.shared.u64 t, %1; cvt.u32.u64 %0, t; }" : "=r"(a) : "l"(p));
    return a;
}
__device__ __forceinline__ void cpasync16(uint32_t dst, const void* src) {
    asm volatile("cp.async.cg.shared.global [%0], [%1], 16;" :: "r"(dst), "l"(src));
}
__device__ __forceinline__ void cp_commit() {
    asm volatile("cp.async.commit_group;" ::: "memory");
}
__device__ __forceinline__ void ldsm_x4(uint32_t addr, uint32_t* r) {
    asm volatile("ldmatrix.sync.aligned.m8n8.x4.shared.b16 {%0,%1,%2,%3}, [%4];"
                 : "=r"(r[0]), "=r"(r[1]), "=r"(r[2]), "=r"(r[3]) : "r"(addr));
}
__device__ __forceinline__ void mma_bf16(float* d, const uint32_t* a, const uint32_t* b) {
    asm volatile(
        "mma.sync.aligned.m16n8k16.row.col.f32.bf16.bf16.f32 "
        "{%0,%1,%2,%3}, {%4,%5,%6,%7}, {%8,%9}, {%0,%1,%2,%3};"
        : "+f"(d[0]), "+f"(d[1]), "+f"(d[2]), "+f"(d[3])
        : "r"(a[0]), "r"(a[1]), "r"(a[2]), "r"(a[3]), "r"(b[0]), "r"(b[1]));
}

// ---------------- K0: transform filters --------------------------------------
__global__ void k0_filters(const float* __restrict__ f1, const float* __restrict__ f2) {
    int idx = blockIdx.x * 256 + threadIdx.x;
    if (idx < 32 * 1024) {
        int f = idx >> 10, ij = idx & 1023, i = ij >> 5, j = ij & 31;
        float s = 0.f;
        for (int p = 0; p < 3; p++)
            for (int q = 0; q < 3; q++) {
                float v = f1[f * 9 + p * 3 + q];
                s += ((__popc(i & p) + __popc(j & q)) & 1) ? -v : v;
            }
        g_kt1[idx] = s * (1.0f / 32768.0f);
    } else {
        int k = idx - 32 * 1024;
        if (k < 64 * 256) {
            int f = k >> 8, ij = k & 255, i = ij >> 4, j = ij & 15;
            float s = 0.f;
            for (int p = 0; p < 3; p++)
                for (int q = 0; q < 3; q++) {
                    float v = f2[f * 9 + p * 3 + q];
                    s += ((__popc(i & p) + __popc(j & q)) & 1) ? -v : v;
                }
            g_kt2[k] = s * (1.0f / 4096.0f);
        }
    }
}

// ---------------- KW: split fc1 weights into bf16 hi/lo -----------------------
__global__ void kw_split(const float* __restrict__ W) {
    int i = (blockIdx.x * 256 + threadIdx.x) * 4;
    float4 v = *(const float4*)(W + i);
    float vv[4] = {v.x, v.y, v.z, v.w};
#pragma unroll
    for (int j = 0; j < 4; j++) {
        __nv_bfloat16 hi = __float2bfloat16(vv[j]);
        g_whi[i + j] = hi;
        g_wlo[i + j] = __float2bfloat16(vv[j] - __bfloat162float(hi));
    }
}

// ---------------- K12: fused layer1 + layer2 (512 threads, 16 warps) ----------
__global__ void __launch_bounds__(512) k12_conv(const float* __restrict__ x,
                                                const float* __restrict__ bias1,
                                                const float* __restrict__ bias2) {
    int b = blockIdx.x, tid = threadIdx.x;
    int w = tid >> 5, lane = tid & 31;
    __shared__ float S[32][33];
    __shared__ float P[16][16][16];

    // ===== phase A: layer 1 =====
    {   // channel sum: 1024 pixels, 2 per thread (float2)
        const float* xb = x + (size_t)b * 3072;
        int e = tid * 2, r = e >> 5, c = e & 31;
        float2 v0 = *(const float2*)(xb + e);
        float2 v1 = *(const float2*)(xb + 1024 + e);
        float2 v2 = *(const float2*)(xb + 2048 + e);
        S[r][c + 0] = v0.x + v1.x + v2.x;
        S[r][c + 1] = v0.y + v1.y + v2.y;
    }
    __syncthreads();
    {   // forward FWHT per row; warp owns rows 2w, 2w+1
        float v0 = S[2 * w + 0][lane], v1 = S[2 * w + 1][lane];
#pragma unroll
        for (int m = 1; m < 32; m <<= 1) {
            float o0 = __shfl_xor_sync(~0u, v0, m), o1 = __shfl_xor_sync(~0u, v1, m);
            bool hi = (lane & m) != 0;
            v0 = hi ? o0 - v0 : o0 + v0; v1 = hi ? o1 - v1 : o1 + v1;
        }
        S[2 * w + 0][lane] = v0; S[2 * w + 1][lane] = v1;
    }
    __syncthreads();
    {   // forward FWHT per column; warp owns cols 2w, 2w+1
        float v0 = S[lane][2 * w + 0], v1 = S[lane][2 * w + 1];
#pragma unroll
        for (int m = 1; m < 32; m <<= 1) {
            float o0 = __shfl_xor_sync(~0u, v0, m), o1 = __shfl_xor_sync(~0u, v1, m);
            bool hi = (lane & m) != 0;
            v0 = hi ? o0 - v0 : o0 + v0; v1 = hi ? o1 - v1 : o1 + v1;
        }
        S[lane][2 * w + 0] = v0; S[lane][2 * w + 1] = v1;
    }
    __syncthreads();

    {
        float sreg[32];
#pragma unroll
        for (int r = 0; r < 32; r++) sreg[r] = S[r][lane];
        float acc[16];
#pragma unroll
        for (int k = 0; k < 16; k++) acc[k] = 0.f;

#pragma unroll 1
        for (int ff = 0; ff < 2; ff++) {
            int f = w + ff * 16;
            const float* kt = g_kt1 + f * 1024;
            float t[32];
#pragma unroll
            for (int r = 0; r < 32; r++) t[r] = sreg[r] * __ldg(kt + r * 32 + lane);
#pragma unroll
            for (int m = 1; m < 32; m <<= 1) {  // inverse: in-register (rows)
#pragma unroll
                for (int r = 0; r < 32; r++)
                    if (!(r & m)) { float a = t[r], c = t[r | m]; t[r] = a + c; t[r | m] = a - c; }
            }
#pragma unroll
            for (int m = 1; m < 32; m <<= 1) {  // inverse: cross-lane (cols)
                bool hi = (lane & m) != 0;
#pragma unroll
                for (int r = 0; r < 32; r++) {
                    float o = __shfl_xor_sync(~0u, t[r], m);
                    t[r] = hi ? o - t[r] : o + t[r];
                }
            }
            float bf = __ldg(bias1 + f);
#pragma unroll
            for (int k = 0; k < 16; k++) {
                float pm = fmaxf(t[2 * k], t[2 * k + 1]);
                pm = fmaxf(pm, __shfl_xor_sync(~0u, pm, 1));
                acc[k] += fmaxf(pm + bf, 0.f);
            }
        }
        if (!(lane & 1)) {
            int c = lane >> 1;
#pragma unroll
            for (int k = 0; k < 16; k++) P[w][k][c] = acc[k];
        }
    }
    __syncthreads();
    // reduce 16 warp-partials -> s2 (stored into S[0..15][0..15])
    if (tid < 256) {
        int k = tid >> 4, c = tid & 15;
        float s = 0.f;
#pragma unroll
        for (int ww = 0; ww < 16; ww++) s += P[ww][k][c];
        S[k][c] = s;
    }
    __syncthreads();

    // ===== phase B: layer 2 (on 16x16 in S) =====
    {   // forward FWHT per row; warp w owns row w
        int c = lane & 15;
        float v = S[w][c];
#pragma unroll
        for (int m = 1; m < 16; m <<= 1) {
            float o = __shfl_xor_sync(~0u, v, m);
            v = ((lane & m) != 0) ? o - v : o + v;
        }
        if (lane < 16) S[w][c] = v;
    }
    __syncthreads();
    {   // forward FWHT per column; warp w owns col w
        int r = lane & 15;
        float v = S[r][w];
#pragma unroll
        for (int m = 1; m < 16; m <<= 1) {
            float o = __shfl_xor_sync(~0u, v, m);
            v = ((lane & m) != 0) ? o - v : o + v;
        }
        if (lane < 16) S[r][w] = v;
    }
    __syncthreads();

    int col = lane & 15;
    float sreg2[16];
#pragma unroll
    for (int r = 0; r < 16; r++) sreg2[r] = S[r][col];

#pragma unroll 1
    for (int ff = 0; ff < 2; ff++) {
        int f = w * 4 + ff * 2 + (lane >> 4);   // half-warp per filter
        const float* kt = g_kt2 + f * 256;
        float t[16];
#pragma unroll
        for (int r = 0; r < 16; r++) t[r] = sreg2[r] * __ldg(kt + r * 16 + col);
#pragma unroll
        for (int m = 1; m < 16; m <<= 1) {
#pragma unroll
            for (int r = 0; r < 16; r++)
                if (!(r & m)) { float a = t[r], c = t[r | m]; t[r] = a + c; t[r | m] = a - c; }
        }
#pragma unroll
        for (int m = 1; m < 16; m <<= 1) {
            bool hi = (lane & m) != 0;
#pragma unroll
            for (int r = 0; r < 16; r++) {
                float o = __shfl_xor_sync(~0u, t[r], m);
                t[r] = hi ? o - t[r] : o + t[r];
            }
        }
        float bf = __ldg(bias2 + f);
        size_t ob = (size_t)b * 4096 + f * 64;
#pragma unroll
        for (int k = 0; k < 8; k++) {
            float pm = fmaxf(t[2 * k], t[2 * k + 1]);
            pm = fmaxf(pm, __shfl_xor_sync(~0u, pm, 1));
            if (!(lane & 1)) {
                float v = fmaxf(pm + bf, 0.f);
                __nv_bfloat16 hi = __float2bfloat16(v);
                size_t o = ob + k * 8 + (col >> 1);
                g_ahi[o] = hi;
                g_alo[o] = __float2bfloat16(v - __bfloat162float(hi));
            }
        }
    }
}

// ---------------- K3: FC1 GEMM via mma.sync bf16 (3-pass hi/lo) ---------------
// Grid (16,8): tile M=128, N=64; K=4096 in 64 chunks of 64.
// Stage layout (49152 B): AH[128][64] @0, AL @16384, BH[64][64] @32768, BL @40960.
#define STG 49152
#define NCH 64

__global__ void __launch_bounds__(256) k3_fc1(const float* __restrict__ fc1b) {
    extern __shared__ char smem[];
    uint32_t sb = smem_u32(smem);
    int tid = threadIdx.x, wid = tid >> 5, lane = tid & 31;
    int mt = blockIdx.x, nt = blockIdx.y;
    int wm = wid & 3, wn = wid >> 2;

    float acc[2][4][4];
#pragma unroll
    for (int a = 0; a < 2; a++)
#pragma unroll
        for (int b = 0; b < 4; b++)
#pragma unroll
            for (int c = 0; c < 4; c++) acc[a][b][c] = 0.f;

    auto load_chunk = [&](int c, int s) {
        uint32_t st = sb + s * STG;
        int kc = c * 64;
#pragma unroll
        for (int p = 0; p < 2; p++) {
            const char* asrc = (const char*)((p ? g_alo : g_ahi) + (size_t)mt * 128 * 4096 + kc);
#pragma unroll
            for (int j = 0; j < 4; j++) {
                int u = tid + j * 256, row = u >> 3, ck = u & 7;
                cpasync16(st + p * 16384 + row * 128 + ((ck ^ (row & 7)) * 16),
                          asrc + (size_t)row * 8192 + ck * 16);
            }
            const char* bsrc = (const char*)((p ? g_wlo : g_whi) + (size_t)nt * 64 * 4096 + kc);
#pragma unroll
            for (int j = 0; j < 2; j++) {
                int u = tid + j * 256, row = u >> 3, ck = u & 7;
                cpasync16(st + 32768 + p * 8192 + row * 128 + ((ck ^ (row & 7)) * 16),
                          bsrc + (size_t)row * 8192 + ck * 16);
            }
        }
        cp_commit();
    };

    load_chunk(0, 0);

    for (int i = 0; i < NCH; i++) {
        int s = i & 1;
        if (i + 1 < NCH) {
            load_chunk(i + 1, s ^ 1);
            asm volatile("cp.async.wait_group 1;" ::: "memory");
        } else {
            asm volatile("cp.async.wait_group 0;" ::: "memory");
        }
        __syncthreads();

        uint32_t st = sb + s * STG;
#pragma unroll
        for (int ks = 0; ks < 4; ks++) {
            uint32_t ah[2][4], al[2][4], bh[2][4], bl[2][4];
#pragma unroll
            for (int tm = 0; tm < 2; tm++) {
                int row = wm * 32 + tm * 16 + (lane & 15);
                int ck = ks * 2 + (lane >> 4);
                uint32_t off = row * 128 + ((ck ^ (row & 7)) * 16);
                ldsm_x4(st + off, ah[tm]);
                ldsm_x4(st + 16384 + off, al[tm]);
            }
#pragma unroll
            for (int tn = 0; tn < 2; tn++) {
                int n = wn * 32 + tn * 16 + (lane & 7) + ((lane >> 4) << 3);
                int ck = ks * 2 + ((lane >> 3) & 1);
                uint32_t off = n * 128 + ((ck ^ (n & 7)) * 16);
                ldsm_x4(st + 32768 + off, bh[tn]);
                ldsm_x4(st + 40960 + off, bl[tn]);
            }
#pragma unroll
            for (int tm = 0; tm < 2; tm++)
#pragma unroll
                for (int j = 0; j < 4; j++) {
                    float* d = acc[tm][j];
                    const uint32_t* Bh = &bh[j >> 1][(j & 1) * 2];
                    const uint32_t* Bl = &bl[j >> 1][(j & 1) * 2];
                    mma_bf16(d, ah[tm], Bh);
                    mma_bf16(d, ah[tm], Bl);
                    mma_bf16(d, al[tm], Bh);
                }
        }
        __syncthreads();
    }

    int g = lane >> 2, t = lane & 3;
#pragma unroll
    for (int tm = 0; tm < 2; tm++)
#pragma unroll
        for (int j = 0; j < 4; j++) {
            int row0 = mt * 128 + wm * 32 + tm * 16 + g;
            int col = nt * 64 + wn * 32 + (j >> 1) * 16 + (j & 1) * 8 + 2 * t;
            float b0 = __ldg(fc1b + col), b1 = __ldg(fc1b + col + 1);
            float* o0 = g_h + (size_t)row0 * 512 + col;
            o0[0] = fmaxf(acc[tm][j][0] + b0, 0.f);
            o0[1] = fmaxf(acc[tm][j][1] + b1, 0.f);
            float* o1 = g_h + (size_t)(row0 + 8) * 512 + col;
            o1[0] = fmaxf(acc[tm][j][2] + b0, 0.f);
            o1[1] = fmaxf(acc[tm][j][3] + b1, 0.f);
        }
}

// ---------------- K4: FC2 + softmax (warp per image) --------------------------
__global__ void __launch_bounds__(256) k4_fc2(const float* __restrict__ w,
                                              const float* __restrict__ fc2b,
                                              float* __restrict__ out) {
    int warp = (blockIdx.x * blockDim.x + threadIdx.x) >> 5;
    int lane = threadIdx.x & 31;
    const float* h0 = g_h + (size_t)warp * 512;
    float xl[16];
#pragma unroll
    for (int j = 0; j < 16; j++) xl[j] = h0[lane + j * 32];
    float l[10];
#pragma unroll
    for (int o = 0; o < 10; o++) {
        float a = 0.f;
#pragma unroll
        for (int j = 0; j < 16; j++) a += xl[j] * __ldg(w + o * 512 + lane + j * 32);
#pragma unroll
        for (int m = 16; m >= 1; m >>= 1) a += __shfl_xor_sync(~0u, a, m);
        l[o] = a + __ldg(fc2b + o);
    }
    float mx = l[0];
#pragma unroll
    for (int o = 1; o < 10; o++) mx = fmaxf(mx, l[o]);
    float s = 0.f;
#pragma unroll
    for (int o = 0; o < 10; o++) { l[o] = __expf(l[o] - mx); s += l[o]; }
    float inv = 1.f / s;
    if (lane < 10) out[(size_t)warp * 10 + lane] = l[lane] * inv;
}

// ---------------- launch ------------------------------------------------------
extern "C" void kernel_launch(void* const* d_in, const int* in_sizes, int n_in,
                              void* d_out, int out_size) {
    const float* x    = (const float*)d_in[0];
    const float* f1   = (const float*)d_in[1];
    const float* b1   = (const float*)d_in[2];
    const float* f2   = (const float*)d_in[3];
    const float* b2   = (const float*)d_in[4];
    const float* fc1w = (const float*)d_in[5];
    const float* fc1b = (const float*)d_in[6];
    const float* fc2w = (const float*)d_in[7];
    const float* fc2b = (const float*)d_in[8];
    float* out = (float*)d_out;

    const int smem3 = 2 * STG;  // 98304 bytes
    cudaFuncSetAttribute(k3_fc1, cudaFuncAttributeMaxDynamicSharedMemorySize, smem3);

    k0_filters<<<192, 256>>>(f1, f2);
    kw_split<<<2048, 256>>>(fc1w);
    k12_conv<<<2048, 512>>>(x, b1, b2);
    k3_fc1<<<dim3(16, 8), 256, smem3>>>(fc1b);
    k4_fc2<<<256, 256>>>(fc2w, fc2b, out);
}

// round 6
// speedup vs baseline: 1.0584x; 1.0584x over previous
#include <cuda_runtime.h>
#include <cuda_bf16.h>
#include <cstdint>

// ---------------- scratch ----------------------------------------------------
__device__ float g_kt1[32 * 1024];               // FWHT2D(filter1)/32768
__device__ float g_kt2[64 * 256];                // FWHT2D(filter2)/4096
__device__ float g_s2[2048 * 256];               // layer2 input channel-sum
__device__ __nv_bfloat16 g_ahi[2048 * 4096];     // activations hi
__device__ __nv_bfloat16 g_alo[2048 * 4096];     // activations lo
__device__ __nv_bfloat16 g_whi[512 * 4096];      // fc1 weights hi
__device__ __nv_bfloat16 g_wlo[512 * 4096];      // fc1 weights lo
__device__ float g_h[2 * 2048 * 512];            // fc1 partials (2 K-splits)

// ---------------- PTX helpers (baseline ISA only) -----------------------------
__device__ __forceinline__ uint32_t smem_u32(const void* p) {
    uint32_t a;
    asm("{ .reg .u64 t; cvta.to.shared.u64 t, %1; cvt.u32.u64 %0, t; }" : "=r"(a) : "l"(p));
    return a;
}
__device__ __forceinline__ void cpasync16(uint32_t dst, const void* src) {
    asm volatile("cp.async.cg.shared.global [%0], [%1], 16;" :: "r"(dst), "l"(src));
}
__device__ __forceinline__ void cp_commit() {
    asm volatile("cp.async.commit_group;" ::: "memory");
}
__device__ __forceinline__ void ldsm_x4(uint32_t addr, uint32_t* r) {
    asm volatile("ldmatrix.sync.aligned.m8n8.x4.shared.b16 {%0,%1,%2,%3}, [%4];"
                 : "=r"(r[0]), "=r"(r[1]), "=r"(r[2]), "=r"(r[3]) : "r"(addr));
}
__device__ __forceinline__ void mma_bf16(float* d, const uint32_t* a, const uint32_t* b) {
    asm volatile(
        "mma.sync.aligned.m16n8k16.row.col.f32.bf16.bf16.f32 "
        "{%0,%1,%2,%3}, {%4,%5,%6,%7}, {%8,%9}, {%0,%1,%2,%3};"
        : "+f"(d[0]), "+f"(d[1]), "+f"(d[2]), "+f"(d[3])
        : "r"(a[0]), "r"(a[1]), "r"(a[2]), "r"(a[3]), "r"(b[0]), "r"(b[1]));
}

// ---------------- K0: transform filters --------------------------------------
__global__ void k0_filters(const float* __restrict__ f1, const float* __restrict__ f2) {
    int idx = blockIdx.x * 256 + threadIdx.x;
    if (idx < 32 * 1024) {
        int f = idx >> 10, ij = idx & 1023, i = ij >> 5, j = ij & 31;
        float s = 0.f;
        for (int p = 0; p < 3; p++)
            for (int q = 0; q < 3; q++) {
                float v = f1[f * 9 + p * 3 + q];
                s += ((__popc(i & p) + __popc(j & q)) & 1) ? -v : v;
            }
        g_kt1[idx] = s * (1.0f / 32768.0f);
    } else {
        int k = idx - 32 * 1024;
        if (k < 64 * 256) {
            int f = k >> 8, ij = k & 255, i = ij >> 4, j = ij & 15;
            float s = 0.f;
            for (int p = 0; p < 3; p++)
                for (int q = 0; q < 3; q++) {
                    float v = f2[f * 9 + p * 3 + q];
                    s += ((__popc(i & p) + __popc(j & q)) & 1) ? -v : v;
                }
            g_kt2[k] = s * (1.0f / 4096.0f);
        }
    }
}

// ---------------- KW: split fc1 weights into bf16 hi/lo -----------------------
__global__ void kw_split(const float* __restrict__ W) {
    int i = (blockIdx.x * 256 + threadIdx.x) * 4;
    float4 v = *(const float4*)(W + i);
    float vv[4] = {v.x, v.y, v.z, v.w};
#pragma unroll
    for (int j = 0; j < 4; j++) {
        __nv_bfloat16 hi = __float2bfloat16(vv[j]);
        g_whi[i + j] = hi;
        g_wlo[i + j] = __float2bfloat16(vv[j] - __bfloat162float(hi));
    }
}

// ---------------- K1: layer 1 fused -------------------------------------------
__global__ void __launch_bounds__(256) k1_layer1(const float* __restrict__ x,
                                                 const float* __restrict__ bias1) {
    int b = blockIdx.x, tid = threadIdx.x;
    int w = tid >> 5, lane = tid & 31;
    __shared__ float S[32][33];
    __shared__ float P[8][16][16];

    {
        const float* xb = x + (size_t)b * 3072;
        int base = tid * 4, r = base >> 5, c = base & 31;
        float4 v0 = *(const float4*)(xb + base);
        float4 v1 = *(const float4*)(xb + 1024 + base);
        float4 v2 = *(const float4*)(xb + 2048 + base);
        S[r][c + 0] = v0.x + v1.x + v2.x;
        S[r][c + 1] = v0.y + v1.y + v2.y;
        S[r][c + 2] = v0.z + v1.z + v2.z;
        S[r][c + 3] = v0.w + v1.w + v2.w;
    }
    __syncthreads();
    {
        float v0 = S[w * 4 + 0][lane], v1 = S[w * 4 + 1][lane];
        float v2 = S[w * 4 + 2][lane], v3 = S[w * 4 + 3][lane];
#pragma unroll
        for (int m = 1; m < 32; m <<= 1) {
            float o0 = __shfl_xor_sync(~0u, v0, m), o1 = __shfl_xor_sync(~0u, v1, m);
            float o2 = __shfl_xor_sync(~0u, v2, m), o3 = __shfl_xor_sync(~0u, v3, m);
            bool hi = (lane & m) != 0;
            v0 = hi ? o0 - v0 : o0 + v0; v1 = hi ? o1 - v1 : o1 + v1;
            v2 = hi ? o2 - v2 : o2 + v2; v3 = hi ? o3 - v3 : o3 + v3;
        }
        S[w * 4 + 0][lane] = v0; S[w * 4 + 1][lane] = v1;
        S[w * 4 + 2][lane] = v2; S[w * 4 + 3][lane] = v3;
    }
    __syncthreads();
    {
        float v0 = S[lane][w * 4 + 0], v1 = S[lane][w * 4 + 1];
        float v2 = S[lane][w * 4 + 2], v3 = S[lane][w * 4 + 3];
#pragma unroll
        for (int m = 1; m < 32; m <<= 1) {
            float o0 = __shfl_xor_sync(~0u, v0, m), o1 = __shfl_xor_sync(~0u, v1, m);
            float o2 = __shfl_xor_sync(~0u, v2, m), o3 = __shfl_xor_sync(~0u, v3, m);
            bool hi = (lane & m) != 0;
            v0 = hi ? o0 - v0 : o0 + v0; v1 = hi ? o1 - v1 : o1 + v1;
            v2 = hi ? o2 - v2 : o2 + v2; v3 = hi ? o3 - v3 : o3 + v3;
        }
        S[lane][w * 4 + 0] = v0; S[lane][w * 4 + 1] = v1;
        S[lane][w * 4 + 2] = v2; S[lane][w * 4 + 3] = v3;
    }
    __syncthreads();

    float sreg[32];
#pragma unroll
    for (int r = 0; r < 32; r++) sreg[r] = S[r][lane];
    float acc[16];
#pragma unroll
    for (int k = 0; k < 16; k++) acc[k] = 0.f;

#pragma unroll 1
    for (int ff = 0; ff < 4; ff++) {
        int f = w + ff * 8;
        const float* kt = g_kt1 + f * 1024;
        float t[32];
#pragma unroll
        for (int r = 0; r < 32; r++) t[r] = sreg[r] * __ldg(kt + r * 32 + lane);
#pragma unroll
        for (int m = 1; m < 32; m <<= 1) {
#pragma unroll
            for (int r = 0; r < 32; r++)
                if (!(r & m)) { float a = t[r], c = t[r | m]; t[r] = a + c; t[r | m] = a - c; }
        }
#pragma unroll
        for (int m = 1; m < 32; m <<= 1) {
            bool hi = (lane & m) != 0;
#pragma unroll
            for (int r = 0; r < 32; r++) {
                float o = __shfl_xor_sync(~0u, t[r], m);
                t[r] = hi ? o - t[r] : o + t[r];
            }
        }
        float bf = __ldg(bias1 + f);
#pragma unroll
        for (int k = 0; k < 16; k++) {
            float pm = fmaxf(t[2 * k], t[2 * k + 1]);
            pm = fmaxf(pm, __shfl_xor_sync(~0u, pm, 1));
            acc[k] += fmaxf(pm + bf, 0.f);
        }
    }
    if (!(lane & 1)) {
        int c = lane >> 1;
#pragma unroll
        for (int k = 0; k < 16; k++) P[w][k][c] = acc[k];
    }
    __syncthreads();
    {
        int k = tid >> 4, c = tid & 15;
        float s = 0.f;
#pragma unroll
        for (int ww = 0; ww < 8; ww++) s += P[ww][k][c];
        g_s2[(size_t)b * 256 + tid] = s;
    }
}

// ---------------- K2: layer 2 fused, outputs bf16 hi/lo -----------------------
__global__ void __launch_bounds__(256) k2_layer2(const float* __restrict__ bias2) {
    int b = blockIdx.x, tid = threadIdx.x;
    int w = tid >> 5, lane = tid & 31;
    __shared__ float S[16][17];

    S[tid >> 4][tid & 15] = g_s2[(size_t)b * 256 + tid];
    __syncthreads();
    {
        int col = lane & 15;
        float v0 = S[2 * w + 0][col], v1 = S[2 * w + 1][col];
#pragma unroll
        for (int m = 1; m < 16; m <<= 1) {
            float o0 = __shfl_xor_sync(~0u, v0, m), o1 = __shfl_xor_sync(~0u, v1, m);
            bool hi = (lane & m) != 0;
            v0 = hi ? o0 - v0 : o0 + v0; v1 = hi ? o1 - v1 : o1 + v1;
        }
        if (lane < 16) { S[2 * w + 0][col] = v0; S[2 * w + 1][col] = v1; }
    }
    __syncthreads();
    {
        int row = lane & 15;
        float v0 = S[row][2 * w + 0], v1 = S[row][2 * w + 1];
#pragma unroll
        for (int m = 1; m < 16; m <<= 1) {
            float o0 = __shfl_xor_sync(~0u, v0, m), o1 = __shfl_xor_sync(~0u, v1, m);
            bool hi = (lane & m) != 0;
            v0 = hi ? o0 - v0 : o0 + v0; v1 = hi ? o1 - v1 : o1 + v1;
        }
        if (lane < 16) { S[row][2 * w + 0] = v0; S[row][2 * w + 1] = v1; }
    }
    __syncthreads();

    int col = lane & 15;
    float sreg[16];
#pragma unroll
    for (int r = 0; r < 16; r++) sreg[r] = S[r][col];

#pragma unroll 1
    for (int ff = 0; ff < 4; ff++) {
        int f = w * 8 + ff * 2 + (lane >> 4);
        const float* kt = g_kt2 + f * 256;
        float t[16];
#pragma unroll
        for (int r = 0; r < 16; r++) t[r] = sreg[r] * __ldg(kt + r * 16 + col);
#pragma unroll
        for (int m = 1; m < 16; m <<= 1) {
#pragma unroll
            for (int r = 0; r < 16; r++)
                if (!(r & m)) { float a = t[r], c = t[r | m]; t[r] = a + c; t[r | m] = a - c; }
        }
#pragma unroll
        for (int m = 1; m < 16; m <<= 1) {
            bool hi = (lane & m) != 0;
#pragma unroll
            for (int r = 0; r < 16; r++) {
                float o = __shfl_xor_sync(~0u, t[r], m);
                t[r] = hi ? o - t[r] : o + t[r];
            }
        }
        float bf = __ldg(bias2 + f);
        size_t ob = (size_t)b * 4096 + f * 64;
#pragma unroll
        for (int k = 0; k < 8; k++) {
            float pm = fmaxf(t[2 * k], t[2 * k + 1]);
            pm = fmaxf(pm, __shfl_xor_sync(~0u, pm, 1));
            if (!(lane & 1)) {
                float v = fmaxf(pm + bf, 0.f);
                __nv_bfloat16 hi = __float2bfloat16(v);
                size_t o = ob + k * 8 + (col >> 1);
                g_ahi[o] = hi;
                g_alo[o] = __float2bfloat16(v - __bfloat162float(hi));
            }
        }
    }
}

// ---------------- K3: FC1 GEMM via mma.sync bf16 (3-pass hi/lo, K-split 2) ----
// Grid (16,8,2): tile M=128, N=64; each z-slice covers K=2048 in 32 chunks of 64.
// Stage layout (49152 B): AH[128][64] @0, AL @16384, BH[64][64] @32768, BL @40960.
#define STG 49152
#define NCH 32

__global__ void __launch_bounds__(256) k3_fc1(int dummy) {
    extern __shared__ char smem[];
    uint32_t sb = smem_u32(smem);
    int tid = threadIdx.x, wid = tid >> 5, lane = tid & 31;
    int mt = blockIdx.x, nt = blockIdx.y, ks = blockIdx.z;
    int wm = wid & 3, wn = wid >> 2;
    int k0 = ks * 2048;

    float acc[2][4][4];
#pragma unroll
    for (int a = 0; a < 2; a++)
#pragma unroll
        for (int b = 0; b < 4; b++)
#pragma unroll
            for (int c = 0; c < 4; c++) acc[a][b][c] = 0.f;

    auto load_chunk = [&](int c, int s) {
        uint32_t st = sb + s * STG;
        int kc = k0 + c * 64;
#pragma unroll
        for (int p = 0; p < 2; p++) {
            const char* asrc = (const char*)((p ? g_alo : g_ahi) + (size_t)mt * 128 * 4096 + kc);
#pragma unroll
            for (int j = 0; j < 4; j++) {
                int u = tid + j * 256, row = u >> 3, ck = u & 7;
                cpasync16(st + p * 16384 + row * 128 + ((ck ^ (row & 7)) * 16),
                          asrc + (size_t)row * 8192 + ck * 16);
            }
            const char* bsrc = (const char*)((p ? g_wlo : g_whi) + (size_t)nt * 64 * 4096 + kc);
#pragma unroll
            for (int j = 0; j < 2; j++) {
                int u = tid + j * 256, row = u >> 3, ck = u & 7;
                cpasync16(st + 32768 + p * 8192 + row * 128 + ((ck ^ (row & 7)) * 16),
                          bsrc + (size_t)row * 8192 + ck * 16);
            }
        }
        cp_commit();
    };

    load_chunk(0, 0);

    for (int i = 0; i < NCH; i++) {
        int s = i & 1;
        if (i + 1 < NCH) {
            load_chunk(i + 1, s ^ 1);
            asm volatile("cp.async.wait_group 1;" ::: "memory");
        } else {
            asm volatile("cp.async.wait_group 0;" ::: "memory");
        }
        __syncthreads();

        uint32_t st = sb + s * STG;
#pragma unroll
        for (int kq = 0; kq < 4; kq++) {
            uint32_t ah[2][4], al[2][4], bh[2][4], bl[2][4];
#pragma unroll
            for (int tm = 0; tm < 2; tm++) {
                int row = wm * 32 + tm * 16 + (lane & 15);
                int ck = kq * 2 + (lane >> 4);
                uint32_t off = row * 128 + ((ck ^ (row & 7)) * 16);
                ldsm_x4(st + off, ah[tm]);
                ldsm_x4(st + 16384 + off, al[tm]);
            }
#pragma unroll
            for (int tn = 0; tn < 2; tn++) {
                int n = wn * 32 + tn * 16 + (lane & 7) + ((lane >> 4) << 3);
                int ck = kq * 2 + ((lane >> 3) & 1);
                uint32_t off = n * 128 + ((ck ^ (n & 7)) * 16);
                ldsm_x4(st + 32768 + off, bh[tn]);
                ldsm_x4(st + 40960 + off, bl[tn]);
            }
#pragma unroll
            for (int tm = 0; tm < 2; tm++)
#pragma unroll
                for (int j = 0; j < 4; j++) {
                    float* d = acc[tm][j];
                    const uint32_t* Bh = &bh[j >> 1][(j & 1) * 2];
                    const uint32_t* Bl = &bl[j >> 1][(j & 1) * 2];
                    mma_bf16(d, ah[tm], Bh);
                    mma_bf16(d, ah[tm], Bl);
                    mma_bf16(d, al[tm], Bh);
                }
        }
        __syncthreads();
    }

    int g = lane >> 2, t = lane & 3;
    float* hb = g_h + (size_t)ks * 2048 * 512;
#pragma unroll
    for (int tm = 0; tm < 2; tm++)
#pragma unroll
        for (int j = 0; j < 4; j++) {
            int row0 = mt * 128 + wm * 32 + tm * 16 + g;
            int col = nt * 64 + wn * 32 + (j >> 1) * 16 + (j & 1) * 8 + 2 * t;
            float* o0 = hb + (size_t)row0 * 512 + col;
            o0[0] = acc[tm][j][0];
            o0[1] = acc[tm][j][1];
            float* o1 = hb + (size_t)(row0 + 8) * 512 + col;
            o1[0] = acc[tm][j][2];
            o1[1] = acc[tm][j][3];
        }
}

// ---------------- K4: FC2 + softmax (warp per image) --------------------------
__global__ void __launch_bounds__(256) k4_fc2(const float* __restrict__ fc1b,
                                              const float* __restrict__ w,
                                              const float* __restrict__ fc2b,
                                              float* __restrict__ out) {
    int warp = (blockIdx.x * blockDim.x + threadIdx.x) >> 5;
    int lane = threadIdx.x & 31;
    const float* h0 = g_h + (size_t)warp * 512;
    const float* h1 = g_h + 2048 * 512 + (size_t)warp * 512;
    float xl[16];
#pragma unroll
    for (int j = 0; j < 16; j++) {
        int k = lane + j * 32;
        xl[j] = fmaxf(h0[k] + h1[k] + __ldg(fc1b + k), 0.f);
    }
    float l[10];
#pragma unroll
    for (int o = 0; o < 10; o++) {
        float a = 0.f;
#pragma unroll
        for (int j = 0; j < 16; j++) a += xl[j] * __ldg(w + o * 512 + lane + j * 32);
#pragma unroll
        for (int m = 16; m >= 1; m >>= 1) a += __shfl_xor_sync(~0u, a, m);
        l[o] = a + __ldg(fc2b + o);
    }
    float mx = l[0];
#pragma unroll
    for (int o = 1; o < 10; o++) mx = fmaxf(mx, l[o]);
    float s = 0.f;
#pragma unroll
    for (int o = 0; o < 10; o++) { l[o] = __expf(l[o] - mx); s += l[o]; }
    float inv = 1.f / s;
    if (lane < 10) out[(size_t)warp * 10 + lane] = l[lane] * inv;
}

// ---------------- launch ------------------------------------------------------
extern "C" void kernel_launch(void* const* d_in, const int* in_sizes, int n_in,
                              void* d_out, int out_size) {
    const float* x    = (const float*)d_in[0];
    const float* f1   = (const float*)d_in[1];
    const float* b1   = (const float*)d_in[2];
    const float* f2   = (const float*)d_in[3];
    const float* b2   = (const float*)d_in[4];
    const float* fc1w = (const float*)d_in[5];
    const float* fc1b = (const float*)d_in[6];
    const float* fc2w = (const float*)d_in[7];
    const float* fc2b = (const float*)d_in[8];
    float* out = (float*)d_out;

    const int smem3 = 2 * STG;  // 98304 bytes
    cudaFuncSetAttribute(k3_fc1, cudaFuncAttributeMaxDynamicSharedMemorySize, smem3);

    k0_filters<<<192, 256>>>(f1, f2);
    kw_split<<<2048, 256>>>(fc1w);
    k1_layer1<<<2048, 256>>>(x, b1);
    k2_layer2<<<2048, 256>>>(b2);
    k3_fc1<<<dim3(16, 8, 2), 256, smem3>>>(0);
    k4_fc2<<<256, 256>>>(fc1b, fc2w, fc2b, out);
}

// round 7
// speedup vs baseline: 1.2687x; 1.1987x over previous
#include <cuda_runtime.h>
#include <cuda_fp16.h>
#include <cuda_bf16.h>
#include <cstdint>

// ---------------- scratch ----------------------------------------------------
__device__ float g_kt1[32 * 1024];               // FWHT2D(filter1)/32768
__device__ float g_kt2[64 * 256];                // FWHT2D(filter2)/4096
__device__ float g_s2[2048 * 256];               // layer2 input channel-sum
__device__ __half g_a[2048 * 4096];              // activations (fp16)
__device__ __half g_whi[512 * 4096];             // fc1 weights hi (fp16)
__device__ __half g_wlo[512 * 4096];             // fc1 weights lo (fp16)
__device__ float g_h[2 * 2048 * 512];            // fc1 partials (2 K-splits)

// ---------------- PTX helpers (baseline ISA only) -----------------------------
__device__ __forceinline__ uint32_t smem_u32(const void* p) {
    uint32_t a;
    asm("{ .reg .u64 t; cvta.to.shared.u64 t, %1; cvt.u32.u64 %0, t; }" : "=r"(a) : "l"(p));
    return a;
}
__device__ __forceinline__ void cpasync16(uint32_t dst, const void* src) {
    asm volatile("cp.async.cg.shared.global [%0], [%1], 16;" :: "r"(dst), "l"(src));
}
__device__ __forceinline__ void cp_commit() {
    asm volatile("cp.async.commit_group;" ::: "memory");
}
__device__ __forceinline__ void ldsm_x4(uint32_t addr, uint32_t* r) {
    asm volatile("ldmatrix.sync.aligned.m8n8.x4.shared.b16 {%0,%1,%2,%3}, [%4];"
                 : "=r"(r[0]), "=r"(r[1]), "=r"(r[2]), "=r"(r[3]) : "r"(addr));
}
__device__ __forceinline__ void mma_f16(float* d, const uint32_t* a, const uint32_t* b) {
    asm volatile(
        "mma.sync.aligned.m16n8k16.row.col.f32.f16.f16.f32 "
        "{%0,%1,%2,%3}, {%4,%5,%6,%7}, {%8,%9}, {%0,%1,%2,%3};"
        : "+f"(d[0]), "+f"(d[1]), "+f"(d[2]), "+f"(d[3])
        : "r"(a[0]), "r"(a[1]), "r"(a[2]), "r"(a[3]), "r"(b[0]), "r"(b[1]));
}

// ---------------- K0: transform filters --------------------------------------
__global__ void k0_filters(const float* __restrict__ f1, const float* __restrict__ f2) {
    int idx = blockIdx.x * 256 + threadIdx.x;
    if (idx < 32 * 1024) {
        int f = idx >> 10, ij = idx & 1023, i = ij >> 5, j = ij & 31;
        float s = 0.f;
        for (int p = 0; p < 3; p++)
            for (int q = 0; q < 3; q++) {
                float v = f1[f * 9 + p * 3 + q];
                s += ((__popc(i & p) + __popc(j & q)) & 1) ? -v : v;
            }
        g_kt1[idx] = s * (1.0f / 32768.0f);
    } else {
        int k = idx - 32 * 1024;
        if (k < 64 * 256) {
            int f = k >> 8, ij = k & 255, i = ij >> 4, j = ij & 15;
            float s = 0.f;
            for (int p = 0; p < 3; p++)
                for (int q = 0; q < 3; q++) {
                    float v = f2[f * 9 + p * 3 + q];
                    s += ((__popc(i & p) + __popc(j & q)) & 1) ? -v : v;
                }
            g_kt2[k] = s * (1.0f / 4096.0f);
        }
    }
}

// ---------------- KW: split fc1 weights into fp16 hi/lo -----------------------
__global__ void kw_split(const float* __restrict__ W) {
    int i = (blockIdx.x * 256 + threadIdx.x) * 4;
    float4 v = *(const float4*)(W + i);
    float vv[4] = {v.x, v.y, v.z, v.w};
#pragma unroll
    for (int j = 0; j < 4; j++) {
        __half hi = __float2half(vv[j]);
        g_whi[i + j] = hi;
        g_wlo[i + j] = __float2half(vv[j] - __half2float(hi));
    }
}

// ---------------- K1: layer 1 fused -------------------------------------------
__global__ void __launch_bounds__(256) k1_layer1(const float* __restrict__ x,
                                                 const float* __restrict__ bias1) {
    int b = blockIdx.x, tid = threadIdx.x;
    int w = tid >> 5, lane = tid & 31;
    __shared__ float S[32][33];
    __shared__ float P[8][16][16];

    {
        const float* xb = x + (size_t)b * 3072;
        int base = tid * 4, r = base >> 5, c = base & 31;
        float4 v0 = *(const float4*)(xb + base);
        float4 v1 = *(const float4*)(xb + 1024 + base);
        float4 v2 = *(const float4*)(xb + 2048 + base);
        S[r][c + 0] = v0.x + v1.x + v2.x;
        S[r][c + 1] = v0.y + v1.y + v2.y;
        S[r][c + 2] = v0.z + v1.z + v2.z;
        S[r][c + 3] = v0.w + v1.w + v2.w;
    }
    __syncthreads();
    {
        float v0 = S[w * 4 + 0][lane], v1 = S[w * 4 + 1][lane];
        float v2 = S[w * 4 + 2][lane], v3 = S[w * 4 + 3][lane];
#pragma unroll
        for (int m = 1; m < 32; m <<= 1) {
            float o0 = __shfl_xor_sync(~0u, v0, m), o1 = __shfl_xor_sync(~0u, v1, m);
            float o2 = __shfl_xor_sync(~0u, v2, m), o3 = __shfl_xor_sync(~0u, v3, m);
            bool hi = (lane & m) != 0;
            v0 = hi ? o0 - v0 : o0 + v0; v1 = hi ? o1 - v1 : o1 + v1;
            v2 = hi ? o2 - v2 : o2 + v2; v3 = hi ? o3 - v3 : o3 + v3;
        }
        S[w * 4 + 0][lane] = v0; S[w * 4 + 1][lane] = v1;
        S[w * 4 + 2][lane] = v2; S[w * 4 + 3][lane] = v3;
    }
    __syncthreads();
    {
        float v0 = S[lane][w * 4 + 0], v1 = S[lane][w * 4 + 1];
        float v2 = S[lane][w * 4 + 2], v3 = S[lane][w * 4 + 3];
#pragma unroll
        for (int m = 1; m < 32; m <<= 1) {
            float o0 = __shfl_xor_sync(~0u, v0, m), o1 = __shfl_xor_sync(~0u, v1, m);
            float o2 = __shfl_xor_sync(~0u, v2, m), o3 = __shfl_xor_sync(~0u, v3, m);
            bool hi = (lane & m) != 0;
            v0 = hi ? o0 - v0 : o0 + v0; v1 = hi ? o1 - v1 : o1 + v1;
            v2 = hi ? o2 - v2 : o2 + v2; v3 = hi ? o3 - v3 : o3 + v3;
        }
        S[lane][w * 4 + 0] = v0; S[lane][w * 4 + 1] = v1;
        S[lane][w * 4 + 2] = v2; S[lane][w * 4 + 3] = v3;
    }
    __syncthreads();

    float sreg[32];
#pragma unroll
    for (int r = 0; r < 32; r++) sreg[r] = S[r][lane];
    float acc[16];
#pragma unroll
    for (int k = 0; k < 16; k++) acc[k] = 0.f;

#pragma unroll 1
    for (int ff = 0; ff < 4; ff++) {
        int f = w + ff * 8;
        const float* kt = g_kt1 + f * 1024;
        float t[32];
#pragma unroll
        for (int r = 0; r < 32; r++) t[r] = sreg[r] * __ldg(kt + r * 32 + lane);
#pragma unroll
        for (int m = 1; m < 32; m <<= 1) {
#pragma unroll
            for (int r = 0; r < 32; r++)
                if (!(r & m)) { float a = t[r], c = t[r | m]; t[r] = a + c; t[r | m] = a - c; }
        }
#pragma unroll
        for (int m = 1; m < 32; m <<= 1) {
            bool hi = (lane & m) != 0;
#pragma unroll
            for (int r = 0; r < 32; r++) {
                float o = __shfl_xor_sync(~0u, t[r], m);
                t[r] = hi ? o - t[r] : o + t[r];
            }
        }
        float bf = __ldg(bias1 + f);
#pragma unroll
        for (int k = 0; k < 16; k++) {
            float pm = fmaxf(t[2 * k], t[2 * k + 1]);
            pm = fmaxf(pm, __shfl_xor_sync(~0u, pm, 1));
            acc[k] += fmaxf(pm + bf, 0.f);
        }
    }
    if (!(lane & 1)) {
        int c = lane >> 1;
#pragma unroll
        for (int k = 0; k < 16; k++) P[w][k][c] = acc[k];
    }
    __syncthreads();
    {
        int k = tid >> 4, c = tid & 15;
        float s = 0.f;
#pragma unroll
        for (int ww = 0; ww < 8; ww++) s += P[ww][k][c];
        g_s2[(size_t)b * 256 + tid] = s;
    }
}

// ---------------- K2: layer 2 fused, outputs fp16 activations -----------------
__global__ void __launch_bounds__(256) k2_layer2(const float* __restrict__ bias2) {
    int b = blockIdx.x, tid = threadIdx.x;
    int w = tid >> 5, lane = tid & 31;
    __shared__ float S[16][17];

    S[tid >> 4][tid & 15] = g_s2[(size_t)b * 256 + tid];
    __syncthreads();
    {
        int col = lane & 15;
        float v0 = S[2 * w + 0][col], v1 = S[2 * w + 1][col];
#pragma unroll
        for (int m = 1; m < 16; m <<= 1) {
            float o0 = __shfl_xor_sync(~0u, v0, m), o1 = __shfl_xor_sync(~0u, v1, m);
            bool hi = (lane & m) != 0;
            v0 = hi ? o0 - v0 : o0 + v0; v1 = hi ? o1 - v1 : o1 + v1;
        }
        if (lane < 16) { S[2 * w + 0][col] = v0; S[2 * w + 1][col] = v1; }
    }
    __syncthreads();
    {
        int row = lane & 15;
        float v0 = S[row][2 * w + 0], v1 = S[row][2 * w + 1];
#pragma unroll
        for (int m = 1; m < 16; m <<= 1) {
            float o0 = __shfl_xor_sync(~0u, v0, m), o1 = __shfl_xor_sync(~0u, v1, m);
            bool hi = (lane & m) != 0;
            v0 = hi ? o0 - v0 : o0 + v0; v1 = hi ? o1 - v1 : o1 + v1;
        }
        if (lane < 16) { S[row][2 * w + 0] = v0; S[row][2 * w + 1] = v1; }
    }
    __syncthreads();

    int col = lane & 15;
    float sreg[16];
#pragma unroll
    for (int r = 0; r < 16; r++) sreg[r] = S[r][col];

#pragma unroll 1
    for (int ff = 0; ff < 4; ff++) {
        int f = w * 8 + ff * 2 + (lane >> 4);
        const float* kt = g_kt2 + f * 256;
        float t[16];
#pragma unroll
        for (int r = 0; r < 16; r++) t[r] = sreg[r] * __ldg(kt + r * 16 + col);
#pragma unroll
        for (int m = 1; m < 16; m <<= 1) {
#pragma unroll
            for (int r = 0; r < 16; r++)
                if (!(r & m)) { float a = t[r], c = t[r | m]; t[r] = a + c; t[r | m] = a - c; }
        }
#pragma unroll
        for (int m = 1; m < 16; m <<= 1) {
            bool hi = (lane & m) != 0;
#pragma unroll
            for (int r = 0; r < 16; r++) {
                float o = __shfl_xor_sync(~0u, t[r], m);
                t[r] = hi ? o - t[r] : o + t[r];
            }
        }
        float bf = __ldg(bias2 + f);
        size_t ob = (size_t)b * 4096 + f * 64;
#pragma unroll
        for (int k = 0; k < 8; k++) {
            float pm = fmaxf(t[2 * k], t[2 * k + 1]);
            pm = fmaxf(pm, __shfl_xor_sync(~0u, pm, 1));
            if (!(lane & 1)) {
                float v = fmaxf(pm + bf, 0.f);
                g_a[ob + k * 8 + (col >> 1)] = __float2half(v);
            }
        }
    }
}

// ---------------- K3: FC1 GEMM via mma.sync fp16 (2-pass, K-split 2) ----------
// Grid (16,8,2): tile M=128, N=64; each z-slice covers K=2048 in 32 chunks of 64.
// Stage (32768 B): A[128][64] fp16 @0 (16K), BH[64][64] @16384 (8K), BL @24576 (8K).
#define STG 32768
#define NCH 32

__global__ void __launch_bounds__(256) k3_fc1(int dummy) {
    extern __shared__ char smem[];
    uint32_t sb = smem_u32(smem);
    int tid = threadIdx.x, wid = tid >> 5, lane = tid & 31;
    int mt = blockIdx.x, nt = blockIdx.y, ks = blockIdx.z;
    int wm = wid & 3, wn = wid >> 2;
    int k0 = ks * 2048;

    float acc[2][4][4];
#pragma unroll
    for (int a = 0; a < 2; a++)
#pragma unroll
        for (int b = 0; b < 4; b++)
#pragma unroll
            for (int c = 0; c < 4; c++) acc[a][b][c] = 0.f;

    auto load_chunk = [&](int c, int s) {
        uint32_t st = sb + s * STG;
        int kc = k0 + c * 64;
        const char* asrc = (const char*)(g_a + (size_t)mt * 128 * 4096 + kc);
#pragma unroll
        for (int j = 0; j < 4; j++) {
            int u = tid + j * 256, row = u >> 3, ck = u & 7;
            cpasync16(st + row * 128 + ((ck ^ (row & 7)) * 16),
                      asrc + (size_t)row * 8192 + ck * 16);
        }
#pragma unroll
        for (int p = 0; p < 2; p++) {
            const char* bsrc = (const char*)((p ? g_wlo : g_whi) + (size_t)nt * 64 * 4096 + kc);
#pragma unroll
            for (int j = 0; j < 2; j++) {
                int u = tid + j * 256, row = u >> 3, ck = u & 7;
                cpasync16(st + 16384 + p * 8192 + row * 128 + ((ck ^ (row & 7)) * 16),
                          bsrc + (size_t)row * 8192 + ck * 16);
            }
        }
        cp_commit();
    };

    load_chunk(0, 0);

    for (int i = 0; i < NCH; i++) {
        int s = i & 1;
        if (i + 1 < NCH) {
            load_chunk(i + 1, s ^ 1);
            asm volatile("cp.async.wait_group 1;" ::: "memory");
        } else {
            asm volatile("cp.async.wait_group 0;" ::: "memory");
        }
        __syncthreads();

        uint32_t st = sb + s * STG;
#pragma unroll
        for (int kq = 0; kq < 4; kq++) {
            uint32_t ah[2][4], bh[2][4], bl[2][4];
#pragma unroll
            for (int tm = 0; tm < 2; tm++) {
                int row = wm * 32 + tm * 16 + (lane & 15);
                int ck = kq * 2 + (lane >> 4);
                uint32_t off = row * 128 + ((ck ^ (row & 7)) * 16);
                ldsm_x4(st + off, ah[tm]);
            }
#pragma unroll
            for (int tn = 0; tn < 2; tn++) {
                int n = wn * 32 + tn * 16 + (lane & 7) + ((lane >> 4) << 3);
                int ck = kq * 2 + ((lane >> 3) & 1);
                uint32_t off = n * 128 + ((ck ^ (n & 7)) * 16);
                ldsm_x4(st + 16384 + off, bh[tn]);
                ldsm_x4(st + 24576 + off, bl[tn]);
            }
#pragma unroll
            for (int tm = 0; tm < 2; tm++)
#pragma unroll
                for (int j = 0; j < 4; j++) {
                    float* d = acc[tm][j];
                    const uint32_t* Bh = &bh[j >> 1][(j & 1) * 2];
                    const uint32_t* Bl = &bl[j >> 1][(j & 1) * 2];
                    mma_f16(d, ah[tm], Bh);
                    mma_f16(d, ah[tm], Bl);
                }
        }
        __syncthreads();
    }

    int g = lane >> 2, t = lane & 3;
    float* hb = g_h + (size_t)ks * 2048 * 512;
#pragma unroll
    for (int tm = 0; tm < 2; tm++)
#pragma unroll
        for (int j = 0; j < 4; j++) {
            int row0 = mt * 128 + wm * 32 + tm * 16 + g;
            int col = nt * 64 + wn * 32 + (j >> 1) * 16 + (j & 1) * 8 + 2 * t;
            float* o0 = hb + (size_t)row0 * 512 + col;
            o0[0] = acc[tm][j][0];
            o0[1] = acc[tm][j][1];
            float* o1 = hb + (size_t)(row0 + 8) * 512 + col;
            o1[0] = acc[tm][j][2];
            o1[1] = acc[tm][j][3];
        }
}

// ---------------- K4: FC2 + softmax (warp per image) --------------------------
__global__ void __launch_bounds__(256) k4_fc2(const float* __restrict__ fc1b,
                                              const float* __restrict__ w,
                                              const float* __restrict__ fc2b,
                                              float* __restrict__ out) {
    int warp = (blockIdx.x * blockDim.x + threadIdx.x) >> 5;
    int lane = threadIdx.x & 31;
    const float* h0 = g_h + (size_t)warp * 512;
    const float* h1 = g_h + 2048 * 512 + (size_t)warp * 512;
    float xl[16];
#pragma unroll
    for (int j = 0; j < 16; j++) {
        int k = lane + j * 32;
        xl[j] = fmaxf(h0[k] + h1[k] + __ldg(fc1b + k), 0.f);
    }
    float l[10];
#pragma unroll
    for (int o = 0; o < 10; o++) {
        float a = 0.f;
#pragma unroll
        for (int j = 0; j < 16; j++) a += xl[j] * __ldg(w + o * 512 + lane + j * 32);
#pragma unroll
        for (int m = 16; m >= 1; m >>= 1) a += __shfl_xor_sync(~0u, a, m);
        l[o] = a + __ldg(fc2b + o);
    }
    float mx = l[0];
#pragma unroll
    for (int o = 1; o < 10; o++) mx = fmaxf(mx, l[o]);
    float s = 0.f;
#pragma unroll
    for (int o = 0; o < 10; o++) { l[o] = __expf(l[o] - mx); s += l[o]; }
    float inv = 1.f / s;
    if (lane < 10) out[(size_t)warp * 10 + lane] = l[lane] * inv;
}

// ---------------- launch ------------------------------------------------------
extern "C" void kernel_launch(void* const* d_in, const int* in_sizes, int n_in,
                              void* d_out, int out_size) {
    const float* x    = (const float*)d_in[0];
    const float* f1   = (const float*)d_in[1];
    const float* b1   = (const float*)d_in[2];
    const float* f2   = (const float*)d_in[3];
    const float* b2   = (const float*)d_in[4];
    const float* fc1w = (const float*)d_in[5];
    const float* fc1b = (const float*)d_in[6];
    const float* fc2w = (const float*)d_in[7];
    const float* fc2b = (const float*)d_in[8];
    float* out = (float*)d_out;

    const int smem3 = 2 * STG;  // 65536 bytes
    cudaFuncSetAttribute(k3_fc1, cudaFuncAttributeMaxDynamicSharedMemorySize, smem3);

    k0_filters<<<192, 256>>>(f1, f2);
    kw_split<<<2048, 256>>>(fc1w);
    k1_layer1<<<2048, 256>>>(x, b1);
    k2_layer2<<<2048, 256>>>(b2);
    k3_fc1<<<dim3(16, 8, 2), 256, smem3>>>(0);
    k4_fc2<<<256, 256>>>(fc1b, fc2w, fc2b, out);
}